// round 1
// baseline (speedup 1.0000x reference)
#include <cuda_runtime.h>
#include <cstdint>
#include <cstddef>

#define TSTEPS 512
#define NB     128        // batch
#define DIN    1024       // input size
#define DH     1024       // hidden
#define NR     256        // rank
#define N4     4096       // 4*DH
#define NSPAR  768        // DH-NR

// ---- device scratch (no dynamic allocation allowed) ----
__device__ float g_Wx[(size_t)N4 * DIN];                 // 16 MB  combined x weights [n][k]
__device__ float g_Wh[(size_t)N4 * DH];                  // 16 MB  combined h weights [n][k]
__device__ float g_bias[N4];
__device__ float g_preX[(size_t)TSTEPS * NB * N4];       // 1 GiB  x-side preactivations (+bias)
__device__ float g_h[2][NB * DH];                        // h ping-pong
__device__ float g_c[NB * DH];                           // cell state

// ---------------- helpers ----------------
__device__ __forceinline__ uint32_t f2tf32(float f) {
    uint32_t u;
    asm("cvt.rna.tf32.f32 %0, %1;" : "=r"(u) : "f"(f));
    return u;
}

__device__ __forceinline__ void mma_tf32(float* c, const uint32_t* a, const uint32_t* b) {
    asm volatile(
        "mma.sync.aligned.m16n8k8.row.col.f32.tf32.tf32.f32 "
        "{%0,%1,%2,%3}, {%4,%5,%6,%7}, {%8,%9}, {%0,%1,%2,%3};"
        : "+f"(c[0]), "+f"(c[1]), "+f"(c[2]), "+f"(c[3])
        : "r"(a[0]), "r"(a[1]), "r"(a[2]), "r"(a[3]), "r"(b[0]), "r"(b[1]));
}

__device__ __forceinline__ float fsigmoid(float x) {
    return 1.0f / (1.0f + __expf(-x));
}

// ---------------- init state ----------------
__global__ void k_init(const float* __restrict__ h0, const float* __restrict__ c0) {
    int i = blockIdx.x * blockDim.x + threadIdx.x;
    if (i < NB * DH) { g_h[0][i] = h0[i]; g_c[i] = c0[i]; }
}

// ---------------- rich rows (copy A) + bias ----------------
__global__ void k_rich_bias(const float* __restrict__ Ax, const float* __restrict__ Ah,
                            const float* __restrict__ bx, const float* __restrict__ bh) {
    int i = blockIdx.x * blockDim.x + threadIdx.x;     // over 4*NR*DIN
    if (i < 4 * NR * DIN) {
        int k   = i % DIN;
        int row = i / DIN;          // g*NR + j
        int g = row / NR, j = row % NR;
        size_t w = ((size_t)(g * DH + j)) * DIN + k;
        g_Wx[w] = Ax[i];
        g_Wh[w] = Ah[i];
    }
    if (i < N4) g_bias[i] = bx[i] + bh[i];
}

// ---------------- sparse rows: W[g*DH+NR+m][k] = sum_r B[g][m][r]*C[g][r][k] ----------------
// grid: (DIN/128, NSPAR/8, 8)  z<4 -> x-branch gate z ; z>=4 -> h-branch gate z-4
__global__ void k_spar(const float* __restrict__ Bx, const float* __restrict__ Cx,
                       const float* __restrict__ Bh, const float* __restrict__ Ch) {
    int z = blockIdx.z;
    int g = z & 3;
    const float* Bp = (z < 4) ? Bx : Bh;
    const float* Cp = (z < 4) ? Cx : Ch;
    float*       Wp = (z < 4) ? g_Wx : g_Wh;
    int m0  = blockIdx.y * 8;
    int col = blockIdx.x * 128 + threadIdx.x;

    __shared__ float Bs[8][NR];
    for (int i = threadIdx.x; i < 8 * NR; i += 128) {
        int mm = i / NR, rr = i % NR;
        Bs[mm][rr] = Bp[(size_t)(g * NSPAR + m0 + mm) * NR + rr];
    }
    __syncthreads();

    float acc[8];
#pragma unroll
    for (int mm = 0; mm < 8; mm++) acc[mm] = 0.0f;
    for (int r = 0; r < NR; ++r) {
        float cv = Cp[(size_t)(g * NR + r) * DIN + col];
#pragma unroll
        for (int mm = 0; mm < 8; mm++) acc[mm] += Bs[mm][r] * cv;
    }
#pragma unroll
    for (int mm = 0; mm < 8; mm++)
        Wp[(size_t)(g * DH + NR + m0 + mm) * DIN + col] = acc[mm];
}

// ---------------- X GEMM: preX[M=65536, N=4096] = x @ Wx^T + bias  (tf32 mma) ----------------
// BM=128, BN=128, BK=32, 256 threads (8 warps: 2x4), warp tile 64x32
__global__ __launch_bounds__(256) void k_xgemm(const float* __restrict__ x) {
    __shared__ float As[128][36];
    __shared__ float Bs[128][36];
    const int tid  = threadIdx.x;
    const int lane = tid & 31;
    const int warp = tid >> 5;
    const int wm   = warp & 1;       // m offset 64
    const int wn   = warp >> 1;      // n offset 32
    const size_t mBase = (size_t)blockIdx.y * 128;
    const int    nBase = blockIdx.x * 128;
    const int lr = tid >> 3;         // 0..31
    const int lc = (tid & 7) * 4;    // 0,4,...,28

    float acc[4][4][4];
#pragma unroll
    for (int a = 0; a < 4; a++)
#pragma unroll
        for (int b = 0; b < 4; b++)
#pragma unroll
            for (int d = 0; d < 4; d++) acc[a][b][d] = 0.0f;

    float4 ra[4], rb[4];
#pragma unroll
    for (int p = 0; p < 4; p++) {
        int r = lr + p * 32;
        ra[p] = *(const float4*)&x[(mBase + r) * DIN + lc];
        rb[p] = *(const float4*)&g_Wx[((size_t)(nBase + r)) * DIN + lc];
    }

    for (int k0 = 0; k0 < DIN; k0 += 32) {
#pragma unroll
        for (int p = 0; p < 4; p++) {
            int r = lr + p * 32;
            *(float4*)&As[r][lc] = ra[p];
            *(float4*)&Bs[r][lc] = rb[p];
        }
        __syncthreads();
        int kn = k0 + 32;
        if (kn < DIN) {
#pragma unroll
            for (int p = 0; p < 4; p++) {
                int r = lr + p * 32;
                ra[p] = *(const float4*)&x[(mBase + r) * DIN + kn + lc];
                rb[p] = *(const float4*)&g_Wx[((size_t)(nBase + r)) * DIN + kn + lc];
            }
        }
#pragma unroll
        for (int kk = 0; kk < 32; kk += 8) {
            uint32_t af[4][4];
            uint32_t bf[4][2];
#pragma unroll
            for (int mf = 0; mf < 4; mf++) {
                int rb0 = wm * 64 + mf * 16 + (lane >> 2);
                af[mf][0] = f2tf32(As[rb0][kk + (lane & 3)]);
                af[mf][1] = f2tf32(As[rb0 + 8][kk + (lane & 3)]);
                af[mf][2] = f2tf32(As[rb0][kk + 4 + (lane & 3)]);
                af[mf][3] = f2tf32(As[rb0 + 8][kk + 4 + (lane & 3)]);
            }
#pragma unroll
            for (int nf = 0; nf < 4; nf++) {
                int nb0 = wn * 32 + nf * 8 + (lane >> 2);
                bf[nf][0] = f2tf32(Bs[nb0][kk + (lane & 3)]);
                bf[nf][1] = f2tf32(Bs[nb0][kk + 4 + (lane & 3)]);
            }
#pragma unroll
            for (int mf = 0; mf < 4; mf++)
#pragma unroll
                for (int nf = 0; nf < 4; nf++)
                    mma_tf32(acc[mf][nf], af[mf], bf[nf]);
        }
        __syncthreads();
    }

#pragma unroll
    for (int mf = 0; mf < 4; mf++) {
#pragma unroll
        for (int nf = 0; nf < 4; nf++) {
            int r0 = wm * 64 + mf * 16 + (lane >> 2);
            int c0 = wn * 32 + nf * 8 + (lane & 3) * 2;
            int n  = nBase + c0;
            size_t base = (mBase + r0) * (size_t)N4 + n;
            g_preX[base]                       = acc[mf][nf][0] + g_bias[n];
            g_preX[base + 1]                   = acc[mf][nf][1] + g_bias[n + 1];
            g_preX[base + 8 * (size_t)N4]      = acc[mf][nf][2] + g_bias[n];
            g_preX[base + 8 * (size_t)N4 + 1]  = acc[mf][nf][3] + g_bias[n + 1];
        }
    }
}

// ---------------- recurrent step (fused GEMM + LSTM cell) ----------------
// grid 64 CTAs x 256 thr; CTA owns 16 hidden units j0..j0+15 (all 4 gates => 64 N-cols)
// M=128, K=1024. Warp grid 4x2: warp tile 32m x 32n.
__global__ __launch_bounds__(256) void k_step(int t, int src, float* __restrict__ outs) {
    __shared__ float sbuf[128 * 68];   // union: (Hs 128x36 + Ws 64x36) | Ps 128x68
    float (*Hs)[36] = (float(*)[36])sbuf;
    float (*Ws)[36] = (float(*)[36])(sbuf + 128 * 36);
    float (*Ps)[68] = (float(*)[68])sbuf;

    const int tid  = threadIdx.x;
    const int lane = tid & 31;
    const int warp = tid >> 5;
    const int wm   = warp & 3;      // m offset 32
    const int wn   = warp >> 2;     // n offset 32
    const int j0   = blockIdx.x * 16;
    const int lr   = tid >> 3;      // 0..31
    const int lc   = (tid & 7) * 4; // 0..28
    const float* __restrict__ hsrc = g_h[src];

    float acc[2][4][4];
#pragma unroll
    for (int a = 0; a < 2; a++)
#pragma unroll
        for (int b = 0; b < 4; b++)
#pragma unroll
            for (int d = 0; d < 4; d++) acc[a][b][d] = 0.0f;

    float4 rh[4], rw[2];
#pragma unroll
    for (int p = 0; p < 4; p++)
        rh[p] = *(const float4*)&hsrc[(lr + p * 32) * DH + lc];
#pragma unroll
    for (int p = 0; p < 2; p++) {
        int c = lr + p * 32;
        int n = (c >> 4) * DH + j0 + (c & 15);
        rw[p] = *(const float4*)&g_Wh[(size_t)n * DH + lc];
    }

    for (int k0 = 0; k0 < DH; k0 += 32) {
#pragma unroll
        for (int p = 0; p < 4; p++) *(float4*)&Hs[lr + p * 32][lc] = rh[p];
#pragma unroll
        for (int p = 0; p < 2; p++) *(float4*)&Ws[lr + p * 32][lc] = rw[p];
        __syncthreads();
        int kn = k0 + 32;
        if (kn < DH) {
#pragma unroll
            for (int p = 0; p < 4; p++)
                rh[p] = *(const float4*)&hsrc[(lr + p * 32) * DH + kn + lc];
#pragma unroll
            for (int p = 0; p < 2; p++) {
                int c = lr + p * 32;
                int n = (c >> 4) * DH + j0 + (c & 15);
                rw[p] = *(const float4*)&g_Wh[(size_t)n * DH + kn + lc];
            }
        }
#pragma unroll
        for (int kk = 0; kk < 32; kk += 8) {
            uint32_t af[2][4];
            uint32_t bf[4][2];
#pragma unroll
            for (int mf = 0; mf < 2; mf++) {
                int rb0 = wm * 32 + mf * 16 + (lane >> 2);
                af[mf][0] = f2tf32(Hs[rb0][kk + (lane & 3)]);
                af[mf][1] = f2tf32(Hs[rb0 + 8][kk + (lane & 3)]);
                af[mf][2] = f2tf32(Hs[rb0][kk + 4 + (lane & 3)]);
                af[mf][3] = f2tf32(Hs[rb0 + 8][kk + 4 + (lane & 3)]);
            }
#pragma unroll
            for (int nf = 0; nf < 4; nf++) {
                int nb0 = wn * 32 + nf * 8 + (lane >> 2);
                bf[nf][0] = f2tf32(Ws[nb0][kk + (lane & 3)]);
                bf[nf][1] = f2tf32(Ws[nb0][kk + 4 + (lane & 3)]);
            }
#pragma unroll
            for (int mf = 0; mf < 2; mf++)
#pragma unroll
                for (int nf = 0; nf < 4; nf++)
                    mma_tf32(acc[mf][nf], af[mf], bf[nf]);
        }
        __syncthreads();   // also protects Ps aliasing below
    }

    // stage preactivations (pre_h + preX, bias already folded into preX) into Ps
#pragma unroll
    for (int mf = 0; mf < 2; mf++) {
#pragma unroll
        for (int nf = 0; nf < 4; nf++) {
            int r0 = wm * 32 + mf * 16 + (lane >> 2);
            int c0 = wn * 32 + nf * 8 + (lane & 3) * 2;
            int n0 = (c0 >> 4) * DH + j0 + (c0 & 15);
            size_t pb = ((size_t)t * NB + r0) * N4;
            Ps[r0][c0]         = acc[mf][nf][0] + g_preX[pb + n0];
            Ps[r0][c0 + 1]     = acc[mf][nf][1] + g_preX[pb + n0 + 1];
            Ps[r0 + 8][c0]     = acc[mf][nf][2] + g_preX[pb + 8 * (size_t)N4 + n0];
            Ps[r0 + 8][c0 + 1] = acc[mf][nf][3] + g_preX[pb + 8 * (size_t)N4 + n0 + 1];
        }
    }
    __syncthreads();

    // pointwise LSTM cell for this CTA's 16 hidden units
    float* hdst = g_h[src ^ 1];
    for (int e = tid; e < NB * 16; e += 256) {
        int b  = e >> 4;
        int jl = e & 15;
        float f  = fsigmoid(Ps[b][jl]);
        float ii = fsigmoid(Ps[b][16 + jl]);
        float gg = tanhf(Ps[b][32 + jl]);
        float oo = fsigmoid(Ps[b][48 + jl]);
        int j = j0 + jl;
        float cc = f * g_c[b * DH + j] + ii * gg;
        float hh = oo * tanhf(cc);
        g_c[b * DH + j]   = cc;
        hdst[b * DH + j]  = hh;
        outs[((size_t)t * NB + b) * DH + j] = hh;
    }
}

// ---------------- final h,c copy ----------------
__global__ void k_final(float* __restrict__ out) {
    int i = blockIdx.x * blockDim.x + threadIdx.x;
    if (i < NB * DH) {
        out[(size_t)TSTEPS * NB * DH + i]           = g_h[0][i];  // after 512 steps, h lives in buf 0
        out[(size_t)TSTEPS * NB * DH + NB * DH + i] = g_c[i];
    }
}

// ---------------- launch ----------------
extern "C" void kernel_launch(void* const* d_in, const int* in_sizes, int n_in,
                              void* d_out, int out_size) {
    const float* x  = (const float*)d_in[0];
    const float* h0 = (const float*)d_in[1];
    const float* c0 = (const float*)d_in[2];
    const float* Ax = (const float*)d_in[3];
    const float* Bx = (const float*)d_in[4];
    const float* Cx = (const float*)d_in[5];
    const float* Ah = (const float*)d_in[6];
    const float* Bh = (const float*)d_in[7];
    const float* Ch = (const float*)d_in[8];
    const float* bx = (const float*)d_in[9];
    const float* bh = (const float*)d_in[10];
    float* out = (float*)d_out;

    k_init<<<(NB * DH + 255) / 256, 256>>>(h0, c0);
    k_rich_bias<<<(4 * NR * DIN + 255) / 256, 256>>>(Ax, Ah, bx, bh);
    dim3 gs(DIN / 128, NSPAR / 8, 8);
    k_spar<<<gs, 128>>>(Bx, Cx, Bh, Ch);
    dim3 gx(N4 / 128, (TSTEPS * NB) / 128);
    k_xgemm<<<gx, 256>>>(x);
    for (int t = 0; t < TSTEPS; ++t)
        k_step<<<DH / 16, 256>>>(t, t & 1, out);
    k_final<<<(NB * DH + 255) / 256, 256>>>(out);
}